// round 14
// baseline (speedup 1.0000x reference)
#include <cuda_runtime.h>
#include <cuda_fp16.h>
#include <cstdint>

// AWQ int4 dequant + GEMM, fused, persistent, 3-stage pipeline.
// CTA 512 threads, tile 256x128, BK=64, 16 warps of 64x32. 1 CTA/SM, grid=148.
//   A:      f32 [M=4096, K=4096]  -> prepass converts to f16 g_A16
//   qw:     int32 [K, N/8]         nibble j of word -> column p*8+j
//   scales: f32 [K/128, N]
//   C:      f32 [M, N=11008]      (values rounded to f16 grid)

#define BM 256
#define BN 128
#define BK 64

static constexpr int K_DIM    = 4096;
static constexpr int N_DIM    = 11008;
static constexpr int M_TOTAL  = 4096;
static constexpr int PACKED_N = N_DIM / 8;    // 1376
static constexpr int K_TILES  = K_DIM / BK;   // 64
static constexpr int N_BLKS   = N_DIM / BN;   // 86
static constexpr int M_BLKS   = M_TOTAL / BM; // 16
static constexpr int N_TILES_TOTAL = N_BLKS * M_BLKS;  // 1376
static constexpr int GRID     = 148;          // 1 CTA per SM

// dynamic smem (bytes): 3 stages
//   sA: 256 x 72 halves  (row stride 144B) -> 36864 per stage
//   sB:  64 x 136 halves (row stride 272B) -> 17408 per stage
static constexpr int SA_STAGE   = 256 * 72 * 2;        // 36864
static constexpr int SB_BASE    = 3 * SA_STAGE;        // 110592
static constexpr int SB_STAGE   = 64 * 136 * 2;        // 17408
static constexpr int SMEM_TOTAL = SB_BASE + 3 * SB_STAGE;  // 162816

__device__ __align__(16) half g_A16[(size_t)M_TOTAL * K_DIM];

__device__ __forceinline__ unsigned smem_u32(const void* p) {
    return (unsigned)__cvta_generic_to_shared(p);
}

#define LDMATRIX_X4(r0, r1, r2, r3, addr)                                     \
    asm volatile("ldmatrix.sync.aligned.m8n8.x4.shared.b16 {%0,%1,%2,%3}, [%4];" \
                 : "=r"(r0), "=r"(r1), "=r"(r2), "=r"(r3) : "r"(addr))

#define LDMATRIX_X4_T(r0, r1, r2, r3, addr)                                   \
    asm volatile("ldmatrix.sync.aligned.m8n8.x4.trans.shared.b16 {%0,%1,%2,%3}, [%4];" \
                 : "=r"(r0), "=r"(r1), "=r"(r2), "=r"(r3) : "r"(addr))

#define MMA_16816(d0, d1, d2, d3, a0, a1, a2, a3, b0, b1)                     \
    asm volatile("mma.sync.aligned.m16n8k16.row.col.f32.f16.f16.f32 "         \
                 "{%0,%1,%2,%3}, {%4,%5,%6,%7}, {%8,%9}, {%0,%1,%2,%3};"       \
                 : "+f"(d0), "+f"(d1), "+f"(d2), "+f"(d3)                      \
                 : "r"(a0), "r"(a1), "r"(a2), "r"(a3), "r"(b0), "r"(b1))

// ---------------- prepass: A f32 -> f16 ----------------
__global__ void convert_A_kernel(const float* __restrict__ A)
{
    size_t idx = ((size_t)blockIdx.x * blockDim.x + threadIdx.x) * 8;
    float4 v0 = *reinterpret_cast<const float4*>(A + idx);
    float4 v1 = *reinterpret_cast<const float4*>(A + idx + 4);
    uint4 h;
    half2 a = __floats2half2_rn(v0.x, v0.y);
    half2 b = __floats2half2_rn(v0.z, v0.w);
    half2 c = __floats2half2_rn(v1.x, v1.y);
    half2 d = __floats2half2_rn(v1.z, v1.w);
    h.x = *reinterpret_cast<unsigned*>(&a);
    h.y = *reinterpret_cast<unsigned*>(&b);
    h.z = *reinterpret_cast<unsigned*>(&c);
    h.w = *reinterpret_cast<unsigned*>(&d);
    *reinterpret_cast<uint4*>(g_A16 + idx) = h;
}

// ---------------- main GEMM (persistent) ----------------
__global__ __launch_bounds__(512, 1)
void awq_gemm_kernel(const int*   __restrict__ qw,
                     const float* __restrict__ scales,
                     float*       __restrict__ C)
{
    extern __shared__ char smem[];
    const uint32_t sbase = smem_u32(smem);

    const int tid    = threadIdx.x;
    const int lane   = tid & 31;
    const int wid    = tid >> 5;        // 0..15
    const int warp_m = wid & 3;         // 4 m-slabs of 64
    const int warp_n = wid >> 2;        // 4 n-slabs of 32

    // qweight tile: 64 k-rows x 16 words; thread owns rows q_row, q_row+32
    const int q_col = tid & 15;   // 0..15
    const int q_row = tid >> 4;   // 0..31

#define SA_ADDR(buf, row, col)  (sbase + (buf) * SA_STAGE + (row) * 144 + (col) * 2)
#define SB_ADDR(buf, row, col)  (sbase + SB_BASE + (buf) * SB_STAGE + (row) * 272 + (col) * 2)

    const half2 MAGIC = __halves2half2(__ushort_as_half(0x6408), __ushort_as_half(0x6408)); // 1032

    // A fill: 2048 x 16B chunks, 4 per thread; chunk c = tid + j*512
    const int a_row = tid >> 3;         // + j*64
    const int a_col = (tid & 7) * 8;

    half2 sc[4];

#define ISSUE_A(m0v, k0, buf)                                                  \
    do {                                                                       \
        _Pragma("unroll")                                                      \
        for (int jj = 0; jj < 4; jj++) {                                       \
            int row = a_row + jj * 64;                                         \
            unsigned d = SA_ADDR(buf, row, a_col);                             \
            const half* sp_ = g_A16 + (size_t)((m0v) + row) * K_DIM + (k0) + a_col; \
            asm volatile("cp.async.cg.shared.global [%0], [%1], 16;\n" :: "r"(d), "l"(sp_)); \
        }                                                                      \
        asm volatile("cp.async.commit_group;\n");                              \
    } while (0)

#define LOAD_SCALES(g)                                                         \
    do {                                                                       \
        const float* sp = sc_base + (size_t)(g) * N_DIM;                       \
        float4 f0 = *reinterpret_cast<const float4*>(sp);                      \
        float4 f1 = *reinterpret_cast<const float4*>(sp + 4);                  \
        sc[0] = __floats2half2_rn(f0.x, f1.x);                                 \
        sc[1] = __floats2half2_rn(f0.y, f1.y);                                 \
        sc[2] = __floats2half2_rn(f0.z, f1.z);                                 \
        sc[3] = __floats2half2_rn(f0.w, f1.w);                                 \
    } while (0)

#define QLOAD(dst, kt)                                                         \
    do {                                                                       \
        const int* qp = qw_base + (size_t)(kt) * BK * PACKED_N;                \
        (dst)[0] = qp[0];                                                      \
        (dst)[1] = qp[(size_t)32 * PACKED_N];                                  \
    } while (0)

#define DEQUANT_STORE(qv, rrow, buf)                                           \
    do {                                                                       \
        unsigned q = (unsigned)(qv);                                           \
        unsigned t0 = ( q        & 0x000F000Fu) | 0x64006400u;                 \
        unsigned t1 = ((q >> 4)  & 0x000F000Fu) | 0x64006400u;                 \
        unsigned t2 = ((q >> 8)  & 0x000F000Fu) | 0x64006400u;                 \
        unsigned t3 = ((q >> 12) & 0x000F000Fu) | 0x64006400u;                 \
        half2 v0 = __hmul2(__hsub2(*reinterpret_cast<half2*>(&t0), MAGIC), sc[0]); \
        half2 v1 = __hmul2(__hsub2(*reinterpret_cast<half2*>(&t1), MAGIC), sc[1]); \
        half2 v2 = __hmul2(__hsub2(*reinterpret_cast<half2*>(&t2), MAGIC), sc[2]); \
        half2 v3 = __hmul2(__hsub2(*reinterpret_cast<half2*>(&t3), MAGIC), sc[3]); \
        half2 p01 = __halves2half2(__low2half(v0),  __low2half(v1));           \
        half2 p23 = __halves2half2(__low2half(v2),  __low2half(v3));           \
        half2 p45 = __halves2half2(__high2half(v0), __high2half(v1));          \
        half2 p67 = __halves2half2(__high2half(v2), __high2half(v3));          \
        uint4 packed;                                                          \
        packed.x = *reinterpret_cast<unsigned*>(&p01);                         \
        packed.y = *reinterpret_cast<unsigned*>(&p23);                         \
        packed.z = *reinterpret_cast<unsigned*>(&p45);                         \
        packed.w = *reinterpret_cast<unsigned*>(&p67);                         \
        asm volatile("st.shared.v4.b32 [%0], {%1, %2, %3, %4};"                \
                     :: "r"(SB_ADDR(buf, rrow, q_col * 8)),                    \
                        "r"(packed.x), "r"(packed.y), "r"(packed.z), "r"(packed.w) \
                     : "memory");                                              \
    } while (0)

#define MMA_KSTEP(ks, buf)                                                     \
    do {                                                                       \
        unsigned a[4][4];                                                      \
        _Pragma("unroll")                                                      \
        for (int mf = 0; mf < 4; mf++) {                                       \
            int row = warp_m * 64 + mf * 16 + (lane & 15);                     \
            int col = (ks) * 16 + (lane >> 4) * 8;                             \
            unsigned addr = SA_ADDR(buf, row, col);                            \
            LDMATRIX_X4(a[mf][0], a[mf][1], a[mf][2], a[mf][3], addr);         \
        }                                                                      \
        unsigned bfr[4][2];                                                    \
        _Pragma("unroll")                                                      \
        for (int p = 0; p < 2; p++) {                                          \
            int row = (ks) * 16 + (lane & 15);                                 \
            int col = warp_n * 32 + p * 16 + (lane >> 4) * 8;                  \
            unsigned addr = SB_ADDR(buf, row, col);                            \
            unsigned r0, r1, r2, r3;                                           \
            LDMATRIX_X4_T(r0, r1, r2, r3, addr);                               \
            bfr[p * 2 + 0][0] = r0; bfr[p * 2 + 0][1] = r1;                    \
            bfr[p * 2 + 1][0] = r2; bfr[p * 2 + 1][1] = r3;                    \
        }                                                                      \
        _Pragma("unroll")                                                      \
        for (int mf = 0; mf < 4; mf++)                                         \
            _Pragma("unroll")                                                  \
            for (int nf = 0; nf < 4; nf++)                                     \
                MMA_16816(acc[mf][nf][0], acc[mf][nf][1], acc[mf][nf][2], acc[mf][nf][3], \
                          a[mf][0], a[mf][1], a[mf][2], a[mf][3],              \
                          bfr[nf][0], bfr[nf][1]);                             \
    } while (0)

    // ---------------- persistent tile loop ----------------
    for (int t = blockIdx.x; t < N_TILES_TOTAL; t += GRID) {
        const int m_idx = t / N_BLKS;       // consecutive t share m_idx -> L2 A reuse
        const int n_idx = t - m_idx * N_BLKS;
        const int m0 = m_idx * BM;
        const int n0 = n_idx * BN;

        const int*   qw_base = qw + (size_t)q_row * PACKED_N + (n0 >> 3) + q_col;
        const float* sc_base = scales + n0 + q_col * 8;

        float acc[4][4][4];
        #pragma unroll
        for (int i = 0; i < 4; i++)
            #pragma unroll
            for (int j = 0; j < 4; j++)
                #pragma unroll
                for (int l = 0; l < 4; l++) acc[i][j][l] = 0.0f;

        // ---- prologue: stages 0 and 1 ----
        int nq1[2];
        LOAD_SCALES(0);
        {
            int w[2];
            QLOAD(w, 0);
            DEQUANT_STORE(w[0], q_row,      0);
            DEQUANT_STORE(w[1], q_row + 32, 0);
        }
        ISSUE_A(m0, 0, 0);
        ISSUE_A(m0, BK, 1);
        QLOAD(nq1, 1);
        asm volatile("cp.async.wait_group 1;\n");
        __syncthreads();

        #pragma unroll 3
        for (int i = 0; i < K_TILES; i++) {
            const int cur = i % 3;
            const int nxt = (i + 1) % 3;
            const int nn  = (i + 2) % 3;
            const bool hasn1 = (i + 1 < K_TILES);
            const bool hasn2 = (i + 2 < K_TILES);

            int nq2[2];
            if (hasn2) {
                ISSUE_A(m0, (i + 2) * BK, nn);
                QLOAD(nq2, i + 2);
            }
            if (hasn1 && (((i + 1) & 1) == 0)) LOAD_SCALES((i + 1) >> 1);

            MMA_KSTEP(0, cur);
            MMA_KSTEP(1, cur);

            if (hasn1) DEQUANT_STORE(nq1[0], q_row, nxt);

            MMA_KSTEP(2, cur);

            if (hasn1) DEQUANT_STORE(nq1[1], q_row + 32, nxt);

            MMA_KSTEP(3, cur);

            if (hasn2)      asm volatile("cp.async.wait_group 1;\n");
            else if (hasn1) asm volatile("cp.async.wait_group 0;\n");
            __syncthreads();

            nq1[0] = nq2[0]; nq1[1] = nq2[1];
        }

        // ---- epilogue: round to f16 grid, store f32 ----
        const int r  = lane >> 2;
        const int cp = (lane & 3) * 2;
        #pragma unroll
        for (int mf = 0; mf < 4; mf++) {
            const int row_base = m0 + warp_m * 64 + mf * 16;
            #pragma unroll
            for (int nf = 0; nf < 4; nf++) {
                const int col = n0 + warp_n * 32 + nf * 8 + cp;
                float2 lo, hi;
                lo.x = __half2float(__float2half_rn(acc[mf][nf][0]));
                lo.y = __half2float(__float2half_rn(acc[mf][nf][1]));
                hi.x = __half2float(__float2half_rn(acc[mf][nf][2]));
                hi.y = __half2float(__float2half_rn(acc[mf][nf][3]));
                *reinterpret_cast<float2*>(C + (size_t)(row_base + r)     * N_DIM + col) = lo;
                *reinterpret_cast<float2*>(C + (size_t)(row_base + r + 8) * N_DIM + col) = hi;
            }
        }
        // safe: k-loop ended with __syncthreads before next tile's prologue writes
    }
}

extern "C" void kernel_launch(void* const* d_in, const int* in_sizes, int n_in,
                              void* d_out, int out_size)
{
    const float* A      = (const float*)d_in[0];
    const int*   qw     = (const int*)d_in[1];
    const float* scales = (const float*)d_in[2];
    float*       C      = (float*)d_out;

    const size_t total = (size_t)M_TOTAL * K_DIM;
    convert_A_kernel<<<(unsigned)(total / 2048), 256>>>(A);

    cudaFuncSetAttribute(awq_gemm_kernel,
                         cudaFuncAttributeMaxDynamicSharedMemorySize, SMEM_TOTAL);
    awq_gemm_kernel<<<GRID, 512, SMEM_TOTAL>>>(qw, scales, C);
}

// round 15
// speedup vs baseline: 1.0672x; 1.0672x over previous
#include <cuda_runtime.h>
#include <cuda_fp16.h>
#include <cstdint>

// AWQ int4 dequant + GEMM, fused, 3-stage pipelined HMMA, BK=64, persistent CTAs.
// CTA 256 threads, tile 128x128, 8 warps of 64x32. 2 CTAs/SM, grid=296.
// R15 = R10 + streaming C stores (.cs) + non-coherent qw/scale loads (.nc).
//   A:      f32 [M=4096, K=4096]  -> prepass converts to f16 g_A16
//   qw:     int32 [K, N/8]         nibble j of word -> column p*8+j
//   scales: f32 [K/128, N]
//   C:      f32 [M, N=11008]      (values rounded to f16 grid)

#define BM 128
#define BN 128
#define BK 64

static constexpr int K_DIM    = 4096;
static constexpr int N_DIM    = 11008;
static constexpr int M_TOTAL  = 4096;
static constexpr int PACKED_N = N_DIM / 8;    // 1376
static constexpr int K_TILES  = K_DIM / BK;   // 64
static constexpr int N_BLKS   = N_DIM / BN;   // 86
static constexpr int M_BLKS   = M_TOTAL / BM; // 32
static constexpr int N_TILES_TOTAL = N_BLKS * M_BLKS;  // 2752
static constexpr int GRID     = 296;          // 148 SMs x 2 CTAs

// dynamic smem (bytes): 3 stages
static constexpr int SA_STAGE   = 128 * 72 * 2;        // 18432
static constexpr int SB_BASE    = 3 * SA_STAGE;        // 55296
static constexpr int SB_STAGE   = 64 * 136 * 2;        // 17408
static constexpr int SMEM_TOTAL = SB_BASE + 3 * SB_STAGE;  // 107520

__device__ __align__(16) half g_A16[(size_t)M_TOTAL * K_DIM];

__device__ __forceinline__ unsigned smem_u32(const void* p) {
    return (unsigned)__cvta_generic_to_shared(p);
}

__device__ __forceinline__ int ldg_nc_s32(const int* p) {
    int v;
    asm volatile("ld.global.nc.b32 %0, [%1];" : "=r"(v) : "l"(p));
    return v;
}
__device__ __forceinline__ float4 ldg_nc_f4(const float* p) {
    float4 v;
    asm volatile("ld.global.nc.v4.f32 {%0,%1,%2,%3}, [%4];"
                 : "=f"(v.x), "=f"(v.y), "=f"(v.z), "=f"(v.w) : "l"(p));
    return v;
}
__device__ __forceinline__ void stg_cs_f2(float* p, float2 v) {
    asm volatile("st.global.cs.v2.f32 [%0], {%1,%2};" :: "l"(p), "f"(v.x), "f"(v.y) : "memory");
}

#define LDMATRIX_X4(r0, r1, r2, r3, addr)                                     \
    asm volatile("ldmatrix.sync.aligned.m8n8.x4.shared.b16 {%0,%1,%2,%3}, [%4];" \
                 : "=r"(r0), "=r"(r1), "=r"(r2), "=r"(r3) : "r"(addr))

#define LDMATRIX_X4_T(r0, r1, r2, r3, addr)                                   \
    asm volatile("ldmatrix.sync.aligned.m8n8.x4.trans.shared.b16 {%0,%1,%2,%3}, [%4];" \
                 : "=r"(r0), "=r"(r1), "=r"(r2), "=r"(r3) : "r"(addr))

#define MMA_16816(d0, d1, d2, d3, a0, a1, a2, a3, b0, b1)                     \
    asm volatile("mma.sync.aligned.m16n8k16.row.col.f32.f16.f16.f32 "         \
                 "{%0,%1,%2,%3}, {%4,%5,%6,%7}, {%8,%9}, {%0,%1,%2,%3};"       \
                 : "+f"(d0), "+f"(d1), "+f"(d2), "+f"(d3)                      \
                 : "r"(a0), "r"(a1), "r"(a2), "r"(a3), "r"(b0), "r"(b1))

// ---------------- prepass: A f32 -> f16 ----------------
__global__ void convert_A_kernel(const float* __restrict__ A)
{
    size_t idx = ((size_t)blockIdx.x * blockDim.x + threadIdx.x) * 8;
    float4 v0 = *reinterpret_cast<const float4*>(A + idx);
    float4 v1 = *reinterpret_cast<const float4*>(A + idx + 4);
    uint4 h;
    half2 a = __floats2half2_rn(v0.x, v0.y);
    half2 b = __floats2half2_rn(v0.z, v0.w);
    half2 c = __floats2half2_rn(v1.x, v1.y);
    half2 d = __floats2half2_rn(v1.z, v1.w);
    h.x = *reinterpret_cast<unsigned*>(&a);
    h.y = *reinterpret_cast<unsigned*>(&b);
    h.z = *reinterpret_cast<unsigned*>(&c);
    h.w = *reinterpret_cast<unsigned*>(&d);
    *reinterpret_cast<uint4*>(g_A16 + idx) = h;
}

// ---------------- main GEMM (persistent) ----------------
__global__ __launch_bounds__(256, 2)
void awq_gemm_kernel(const int*   __restrict__ qw,
                     const float* __restrict__ scales,
                     float*       __restrict__ C)
{
    extern __shared__ char smem[];
    const uint32_t sbase = smem_u32(smem);

    const int tid    = threadIdx.x;
    const int lane   = tid & 31;
    const int wid    = tid >> 5;
    const int warp_m = wid & 1;
    const int warp_n = wid >> 1;

    const int q_col = tid & 15;   // int32 column within tile
    const int q_row = tid >> 4;   // 0..15 (owns k-rows q_row + 16*r, r=0..3)

#define SA_ADDR(buf, row, col)  (sbase + (buf) * SA_STAGE + (row) * 144 + (col) * 2)
#define SB_ADDR(buf, row, col)  (sbase + SB_BASE + (buf) * SB_STAGE + (row) * 272 + (col) * 2)

    const half2 MAGIC = __halves2half2(__ushort_as_half(0x6408), __ushort_as_half(0x6408)); // 1032

    // A fill: 1024 x 16B chunks, 4 per thread
    const int a_row = tid >> 3;
    const int a_col = (tid & 7) * 8;

    half2 sc[4];

#define ISSUE_A(k0, buf)                                                       \
    do {                                                                       \
        _Pragma("unroll")                                                      \
        for (int j = 0; j < 4; j++) {                                          \
            int row = a_row + j * 32;                                          \
            unsigned d = SA_ADDR(buf, row, a_col);                             \
            const half* s = g_A16 + (size_t)(m0 + row) * K_DIM + (k0) + a_col; \
            asm volatile("cp.async.cg.shared.global [%0], [%1], 16;\n" :: "r"(d), "l"(s)); \
        }                                                                      \
        asm volatile("cp.async.commit_group;\n");                              \
    } while (0)

#define LOAD_SCALES(g)                                                         \
    do {                                                                       \
        const float* sp = sc_base + (size_t)(g) * N_DIM;                       \
        float4 f0 = ldg_nc_f4(sp);                                             \
        float4 f1 = ldg_nc_f4(sp + 4);                                         \
        sc[0] = __floats2half2_rn(f0.x, f1.x);                                 \
        sc[1] = __floats2half2_rn(f0.y, f1.y);                                 \
        sc[2] = __floats2half2_rn(f0.z, f1.z);                                 \
        sc[3] = __floats2half2_rn(f0.w, f1.w);                                 \
    } while (0)

#define QLOAD(dst, kt)                                                         \
    do {                                                                       \
        const int* qp = qw_base + (size_t)(kt) * BK * PACKED_N;                \
        (dst)[0] = ldg_nc_s32(qp);                                             \
        (dst)[1] = ldg_nc_s32(qp + (size_t)16 * PACKED_N);                     \
        (dst)[2] = ldg_nc_s32(qp + (size_t)32 * PACKED_N);                     \
        (dst)[3] = ldg_nc_s32(qp + (size_t)48 * PACKED_N);                     \
    } while (0)

#define DEQUANT_STORE(qv, rrow, buf)                                           \
    do {                                                                       \
        unsigned q = (unsigned)(qv);                                           \
        unsigned t0 = ( q        & 0x000F000Fu) | 0x64006400u;                 \
        unsigned t1 = ((q >> 4)  & 0x000F000Fu) | 0x64006400u;                 \
        unsigned t2 = ((q >> 8)  & 0x000F000Fu) | 0x64006400u;                 \
        unsigned t3 = ((q >> 12) & 0x000F000Fu) | 0x64006400u;                 \
        half2 v0 = __hmul2(__hsub2(*reinterpret_cast<half2*>(&t0), MAGIC), sc[0]); \
        half2 v1 = __hmul2(__hsub2(*reinterpret_cast<half2*>(&t1), MAGIC), sc[1]); \
        half2 v2 = __hmul2(__hsub2(*reinterpret_cast<half2*>(&t2), MAGIC), sc[2]); \
        half2 v3 = __hmul2(__hsub2(*reinterpret_cast<half2*>(&t3), MAGIC), sc[3]); \
        half2 p01 = __halves2half2(__low2half(v0),  __low2half(v1));           \
        half2 p23 = __halves2half2(__low2half(v2),  __low2half(v3));           \
        half2 p45 = __halves2half2(__high2half(v0), __high2half(v1));          \
        half2 p67 = __halves2half2(__high2half(v2), __high2half(v3));          \
        uint4 packed;                                                          \
        packed.x = *reinterpret_cast<unsigned*>(&p01);                         \
        packed.y = *reinterpret_cast<unsigned*>(&p23);                         \
        packed.z = *reinterpret_cast<unsigned*>(&p45);                         \
        packed.w = *reinterpret_cast<unsigned*>(&p67);                         \
        asm volatile("st.shared.v4.b32 [%0], {%1, %2, %3, %4};"                \
                     :: "r"(SB_ADDR(buf, rrow, q_col * 8)),                    \
                        "r"(packed.x), "r"(packed.y), "r"(packed.z), "r"(packed.w) \
                     : "memory");                                              \
    } while (0)

#define MMA_KSTEP(ks, buf)                                                     \
    do {                                                                       \
        unsigned a[4][4];                                                      \
        _Pragma("unroll")                                                      \
        for (int mf = 0; mf < 4; mf++) {                                       \
            int row = warp_m * 64 + mf * 16 + (lane & 15);                     \
            int col = (ks) * 16 + (lane >> 4) * 8;                             \
            unsigned addr = SA_ADDR(buf, row, col);                            \
            LDMATRIX_X4(a[mf][0], a[mf][1], a[mf][2], a[mf][3], addr);         \
        }                                                                      \
        unsigned bfr[4][2];                                                    \
        _Pragma("unroll")                                                      \
        for (int p = 0; p < 2; p++) {                                          \
            int row = (ks) * 16 + (lane & 15);                                 \
            int col = warp_n * 32 + p * 16 + (lane >> 4) * 8;                  \
            unsigned addr = SB_ADDR(buf, row, col);                            \
            unsigned r0, r1, r2, r3;                                           \
            LDMATRIX_X4_T(r0, r1, r2, r3, addr);                               \
            bfr[p * 2 + 0][0] = r0; bfr[p * 2 + 0][1] = r1;                    \
            bfr[p * 2 + 1][0] = r2; bfr[p * 2 + 1][1] = r3;                    \
        }                                                                      \
        _Pragma("unroll")                                                      \
        for (int mf = 0; mf < 4; mf++)                                         \
            _Pragma("unroll")                                                  \
            for (int nf = 0; nf < 4; nf++)                                     \
                MMA_16816(acc[mf][nf][0], acc[mf][nf][1], acc[mf][nf][2], acc[mf][nf][3], \
                          a[mf][0], a[mf][1], a[mf][2], a[mf][3],              \
                          bfr[nf][0], bfr[nf][1]);                             \
    } while (0)

    // ---------------- persistent tile loop ----------------
    for (int t = blockIdx.x; t < N_TILES_TOTAL; t += GRID) {
        const int m_idx = t / N_BLKS;       // consecutive t share m_idx -> L2 A reuse
        const int n_idx = t - m_idx * N_BLKS;
        const int m0 = m_idx * BM;
        const int n0 = n_idx * BN;

        const int*   qw_base = qw + (size_t)q_row * PACKED_N + (n0 >> 3) + q_col;
        const float* sc_base = scales + n0 + q_col * 8;

        float acc[4][4][4];
        #pragma unroll
        for (int i = 0; i < 4; i++)
            #pragma unroll
            for (int j = 0; j < 4; j++)
                #pragma unroll
                for (int l = 0; l < 4; l++) acc[i][j][l] = 0.0f;

        // ---- prologue ----
        int nq1[4];
        LOAD_SCALES(0);
        {
            int w[4];
            QLOAD(w, 0);
            DEQUANT_STORE(w[0], q_row,      0);
            DEQUANT_STORE(w[1], q_row + 16, 0);
            DEQUANT_STORE(w[2], q_row + 32, 0);
            DEQUANT_STORE(w[3], q_row + 48, 0);
        }
        ISSUE_A(0, 0);
        ISSUE_A(BK, 1);
        QLOAD(nq1, 1);
        asm volatile("cp.async.wait_group 1;\n");
        __syncthreads();

        #pragma unroll 3
        for (int i = 0; i < K_TILES; i++) {
            const int cur = i % 3;
            const int nxt = (i + 1) % 3;
            const int nn  = (i + 2) % 3;
            const bool hasn1 = (i + 1 < K_TILES);
            const bool hasn2 = (i + 2 < K_TILES);

            int nq2[4];
            if (hasn2) {
                ISSUE_A((i + 2) * BK, nn);
                QLOAD(nq2, i + 2);
            }
            if (hasn1 && (((i + 1) & 1) == 0)) LOAD_SCALES((i + 1) >> 1);

            MMA_KSTEP(0, cur);
            MMA_KSTEP(1, cur);

            if (hasn1) {
                DEQUANT_STORE(nq1[0], q_row,      nxt);
                DEQUANT_STORE(nq1[1], q_row + 16, nxt);
            }

            MMA_KSTEP(2, cur);

            if (hasn1) {
                DEQUANT_STORE(nq1[2], q_row + 32, nxt);
                DEQUANT_STORE(nq1[3], q_row + 48, nxt);
            }

            MMA_KSTEP(3, cur);

            if (hasn2)      asm volatile("cp.async.wait_group 1;\n");
            else if (hasn1) asm volatile("cp.async.wait_group 0;\n");
            __syncthreads();

            nq1[0] = nq2[0]; nq1[1] = nq2[1]; nq1[2] = nq2[2]; nq1[3] = nq2[3];
        }

        // ---- epilogue: round to f16 grid, streaming f32 stores ----
        const int r  = lane >> 2;
        const int cp = (lane & 3) * 2;
        #pragma unroll
        for (int mf = 0; mf < 4; mf++) {
            const int row_base = m0 + warp_m * 64 + mf * 16;
            #pragma unroll
            for (int nf = 0; nf < 4; nf++) {
                const int col = n0 + warp_n * 32 + nf * 8 + cp;
                float2 lo, hi;
                lo.x = __half2float(__float2half_rn(acc[mf][nf][0]));
                lo.y = __half2float(__float2half_rn(acc[mf][nf][1]));
                hi.x = __half2float(__float2half_rn(acc[mf][nf][2]));
                hi.y = __half2float(__float2half_rn(acc[mf][nf][3]));
                stg_cs_f2(C + (size_t)(row_base + r)     * N_DIM + col, lo);
                stg_cs_f2(C + (size_t)(row_base + r + 8) * N_DIM + col, hi);
            }
        }
    }
}

extern "C" void kernel_launch(void* const* d_in, const int* in_sizes, int n_in,
                              void* d_out, int out_size)
{
    const float* A      = (const float*)d_in[0];
    const int*   qw     = (const int*)d_in[1];
    const float* scales = (const float*)d_in[2];
    float*       C      = (float*)d_out;

    const size_t total = (size_t)M_TOTAL * K_DIM;
    convert_A_kernel<<<(unsigned)(total / 2048), 256>>>(A);

    cudaFuncSetAttribute(awq_gemm_kernel,
                         cudaFuncAttributeMaxDynamicSharedMemorySize, SMEM_TOTAL);
    awq_gemm_kernel<<<GRID, 256, SMEM_TOTAL>>>(qw, scales, C);
}

// round 16
// speedup vs baseline: 1.0678x; 1.0006x over previous
#include <cuda_runtime.h>
#include <cuda_fp16.h>
#include <cstdint>

// AWQ int4 dequant + GEMM, fused, 3-stage pipelined HMMA, BK=64, persistent CTAs.
// CTA 256 threads, tile 128x128, 8 warps of 64x32. 2 CTAs/SM, grid=296.
// R16 = R15 (best: 1025.7us) with QLOAD hoisted above ISSUE_A (earliest issue
// for the longest-latency loads). Streaming C stores (.cs), non-coherent
// qw/scale loads (.nc).
//   A:      f32 [M=4096, K=4096]  -> prepass converts to f16 g_A16
//   qw:     int32 [K, N/8]         nibble j of word -> column p*8+j
//   scales: f32 [K/128, N]
//   C:      f32 [M, N=11008]      (values rounded to f16 grid)

#define BM 128
#define BN 128
#define BK 64

static constexpr int K_DIM    = 4096;
static constexpr int N_DIM    = 11008;
static constexpr int M_TOTAL  = 4096;
static constexpr int PACKED_N = N_DIM / 8;    // 1376
static constexpr int K_TILES  = K_DIM / BK;   // 64
static constexpr int N_BLKS   = N_DIM / BN;   // 86
static constexpr int M_BLKS   = M_TOTAL / BM; // 32
static constexpr int N_TILES_TOTAL = N_BLKS * M_BLKS;  // 2752
static constexpr int GRID     = 296;          // 148 SMs x 2 CTAs

// dynamic smem (bytes): 3 stages
static constexpr int SA_STAGE   = 128 * 72 * 2;        // 18432
static constexpr int SB_BASE    = 3 * SA_STAGE;        // 55296
static constexpr int SB_STAGE   = 64 * 136 * 2;        // 17408
static constexpr int SMEM_TOTAL = SB_BASE + 3 * SB_STAGE;  // 107520

__device__ __align__(16) half g_A16[(size_t)M_TOTAL * K_DIM];

__device__ __forceinline__ unsigned smem_u32(const void* p) {
    return (unsigned)__cvta_generic_to_shared(p);
}

__device__ __forceinline__ int ldg_nc_s32(const int* p) {
    int v;
    asm volatile("ld.global.nc.b32 %0, [%1];" : "=r"(v) : "l"(p));
    return v;
}
__device__ __forceinline__ float4 ldg_nc_f4(const float* p) {
    float4 v;
    asm volatile("ld.global.nc.v4.f32 {%0,%1,%2,%3}, [%4];"
                 : "=f"(v.x), "=f"(v.y), "=f"(v.z), "=f"(v.w) : "l"(p));
    return v;
}
__device__ __forceinline__ void stg_cs_f2(float* p, float2 v) {
    asm volatile("st.global.cs.v2.f32 [%0], {%1,%2};" :: "l"(p), "f"(v.x), "f"(v.y) : "memory");
}

#define LDMATRIX_X4(r0, r1, r2, r3, addr)                                     \
    asm volatile("ldmatrix.sync.aligned.m8n8.x4.shared.b16 {%0,%1,%2,%3}, [%4];" \
                 : "=r"(r0), "=r"(r1), "=r"(r2), "=r"(r3) : "r"(addr))

#define LDMATRIX_X4_T(r0, r1, r2, r3, addr)                                   \
    asm volatile("ldmatrix.sync.aligned.m8n8.x4.trans.shared.b16 {%0,%1,%2,%3}, [%4];" \
                 : "=r"(r0), "=r"(r1), "=r"(r2), "=r"(r3) : "r"(addr))

#define MMA_16816(d0, d1, d2, d3, a0, a1, a2, a3, b0, b1)                     \
    asm volatile("mma.sync.aligned.m16n8k16.row.col.f32.f16.f16.f32 "         \
                 "{%0,%1,%2,%3}, {%4,%5,%6,%7}, {%8,%9}, {%0,%1,%2,%3};"       \
                 : "+f"(d0), "+f"(d1), "+f"(d2), "+f"(d3)                      \
                 : "r"(a0), "r"(a1), "r"(a2), "r"(a3), "r"(b0), "r"(b1))

// ---------------- prepass: A f32 -> f16 ----------------
__global__ void convert_A_kernel(const float* __restrict__ A)
{
    size_t idx = ((size_t)blockIdx.x * blockDim.x + threadIdx.x) * 8;
    float4 v0 = *reinterpret_cast<const float4*>(A + idx);
    float4 v1 = *reinterpret_cast<const float4*>(A + idx + 4);
    uint4 h;
    half2 a = __floats2half2_rn(v0.x, v0.y);
    half2 b = __floats2half2_rn(v0.z, v0.w);
    half2 c = __floats2half2_rn(v1.x, v1.y);
    half2 d = __floats2half2_rn(v1.z, v1.w);
    h.x = *reinterpret_cast<unsigned*>(&a);
    h.y = *reinterpret_cast<unsigned*>(&b);
    h.z = *reinterpret_cast<unsigned*>(&c);
    h.w = *reinterpret_cast<unsigned*>(&d);
    *reinterpret_cast<uint4*>(g_A16 + idx) = h;
}

// ---------------- main GEMM (persistent) ----------------
__global__ __launch_bounds__(256, 2)
void awq_gemm_kernel(const int*   __restrict__ qw,
                     const float* __restrict__ scales,
                     float*       __restrict__ C)
{
    extern __shared__ char smem[];
    const uint32_t sbase = smem_u32(smem);

    const int tid    = threadIdx.x;
    const int lane   = tid & 31;
    const int wid    = tid >> 5;
    const int warp_m = wid & 1;
    const int warp_n = wid >> 1;

    const int q_col = tid & 15;   // int32 column within tile
    const int q_row = tid >> 4;   // 0..15 (owns k-rows q_row + 16*r, r=0..3)

#define SA_ADDR(buf, row, col)  (sbase + (buf) * SA_STAGE + (row) * 144 + (col) * 2)
#define SB_ADDR(buf, row, col)  (sbase + SB_BASE + (buf) * SB_STAGE + (row) * 272 + (col) * 2)

    const half2 MAGIC = __halves2half2(__ushort_as_half(0x6408), __ushort_as_half(0x6408)); // 1032

    // A fill: 1024 x 16B chunks, 4 per thread
    const int a_row = tid >> 3;
    const int a_col = (tid & 7) * 8;

    half2 sc[4];

#define ISSUE_A(k0, buf)                                                       \
    do {                                                                       \
        _Pragma("unroll")                                                      \
        for (int j = 0; j < 4; j++) {                                          \
            int row = a_row + j * 32;                                          \
            unsigned d = SA_ADDR(buf, row, a_col);                             \
            const half* s = g_A16 + (size_t)(m0 + row) * K_DIM + (k0) + a_col; \
            asm volatile("cp.async.cg.shared.global [%0], [%1], 16;\n" :: "r"(d), "l"(s)); \
        }                                                                      \
        asm volatile("cp.async.commit_group;\n");                              \
    } while (0)

#define LOAD_SCALES(g)                                                         \
    do {                                                                       \
        const float* sp = sc_base + (size_t)(g) * N_DIM;                       \
        float4 f0 = ldg_nc_f4(sp);                                             \
        float4 f1 = ldg_nc_f4(sp + 4);                                         \
        sc[0] = __floats2half2_rn(f0.x, f1.x);                                 \
        sc[1] = __floats2half2_rn(f0.y, f1.y);                                 \
        sc[2] = __floats2half2_rn(f0.z, f1.z);                                 \
        sc[3] = __floats2half2_rn(f0.w, f1.w);                                 \
    } while (0)

#define QLOAD(dst, kt)                                                         \
    do {                                                                       \
        const int* qp = qw_base + (size_t)(kt) * BK * PACKED_N;                \
        (dst)[0] = ldg_nc_s32(qp);                                             \
        (dst)[1] = ldg_nc_s32(qp + (size_t)16 * PACKED_N);                     \
        (dst)[2] = ldg_nc_s32(qp + (size_t)32 * PACKED_N);                     \
        (dst)[3] = ldg_nc_s32(qp + (size_t)48 * PACKED_N);                     \
    } while (0)

#define DEQUANT_STORE(qv, rrow, buf)                                           \
    do {                                                                       \
        unsigned q = (unsigned)(qv);                                           \
        unsigned t0 = ( q        & 0x000F000Fu) | 0x64006400u;                 \
        unsigned t1 = ((q >> 4)  & 0x000F000Fu) | 0x64006400u;                 \
        unsigned t2 = ((q >> 8)  & 0x000F000Fu) | 0x64006400u;                 \
        unsigned t3 = ((q >> 12) & 0x000F000Fu) | 0x64006400u;                 \
        half2 v0 = __hmul2(__hsub2(*reinterpret_cast<half2*>(&t0), MAGIC), sc[0]); \
        half2 v1 = __hmul2(__hsub2(*reinterpret_cast<half2*>(&t1), MAGIC), sc[1]); \
        half2 v2 = __hmul2(__hsub2(*reinterpret_cast<half2*>(&t2), MAGIC), sc[2]); \
        half2 v3 = __hmul2(__hsub2(*reinterpret_cast<half2*>(&t3), MAGIC), sc[3]); \
        half2 p01 = __halves2half2(__low2half(v0),  __low2half(v1));           \
        half2 p23 = __halves2half2(__low2half(v2),  __low2half(v3));           \
        half2 p45 = __halves2half2(__high2half(v0), __high2half(v1));          \
        half2 p67 = __halves2half2(__high2half(v2), __high2half(v3));          \
        uint4 packed;                                                          \
        packed.x = *reinterpret_cast<unsigned*>(&p01);                         \
        packed.y = *reinterpret_cast<unsigned*>(&p23);                         \
        packed.z = *reinterpret_cast<unsigned*>(&p45);                         \
        packed.w = *reinterpret_cast<unsigned*>(&p67);                         \
        asm volatile("st.shared.v4.b32 [%0], {%1, %2, %3, %4};"                \
                     :: "r"(SB_ADDR(buf, rrow, q_col * 8)),                    \
                        "r"(packed.x), "r"(packed.y), "r"(packed.z), "r"(packed.w) \
                     : "memory");                                              \
    } while (0)

#define MMA_KSTEP(ks, buf)                                                     \
    do {                                                                       \
        unsigned a[4][4];                                                      \
        _Pragma("unroll")                                                      \
        for (int mf = 0; mf < 4; mf++) {                                       \
            int row = warp_m * 64 + mf * 16 + (lane & 15);                     \
            int col = (ks) * 16 + (lane >> 4) * 8;                             \
            unsigned addr = SA_ADDR(buf, row, col);                            \
            LDMATRIX_X4(a[mf][0], a[mf][1], a[mf][2], a[mf][3], addr);         \
        }                                                                      \
        unsigned bfr[4][2];                                                    \
        _Pragma("unroll")                                                      \
        for (int p = 0; p < 2; p++) {                                          \
            int row = (ks) * 16 + (lane & 15);                                 \
            int col = warp_n * 32 + p * 16 + (lane >> 4) * 8;                  \
            unsigned addr = SB_ADDR(buf, row, col);                            \
            unsigned r0, r1, r2, r3;                                           \
            LDMATRIX_X4_T(r0, r1, r2, r3, addr);                               \
            bfr[p * 2 + 0][0] = r0; bfr[p * 2 + 0][1] = r1;                    \
            bfr[p * 2 + 1][0] = r2; bfr[p * 2 + 1][1] = r3;                    \
        }                                                                      \
        _Pragma("unroll")                                                      \
        for (int mf = 0; mf < 4; mf++)                                         \
            _Pragma("unroll")                                                  \
            for (int nf = 0; nf < 4; nf++)                                     \
                MMA_16816(acc[mf][nf][0], acc[mf][nf][1], acc[mf][nf][2], acc[mf][nf][3], \
                          a[mf][0], a[mf][1], a[mf][2], a[mf][3],              \
                          bfr[nf][0], bfr[nf][1]);                             \
    } while (0)

    // ---------------- persistent tile loop ----------------
    for (int t = blockIdx.x; t < N_TILES_TOTAL; t += GRID) {
        const int m_idx = t / N_BLKS;       // consecutive t share m_idx -> L2 A reuse
        const int n_idx = t - m_idx * N_BLKS;
        const int m0 = m_idx * BM;
        const int n0 = n_idx * BN;

        const int*   qw_base = qw + (size_t)q_row * PACKED_N + (n0 >> 3) + q_col;
        const float* sc_base = scales + n0 + q_col * 8;

        float acc[4][4][4];
        #pragma unroll
        for (int i = 0; i < 4; i++)
            #pragma unroll
            for (int j = 0; j < 4; j++)
                #pragma unroll
                for (int l = 0; l < 4; l++) acc[i][j][l] = 0.0f;

        // ---- prologue ----
        int nq1[4];
        LOAD_SCALES(0);
        {
            int w[4];
            QLOAD(w, 0);
            DEQUANT_STORE(w[0], q_row,      0);
            DEQUANT_STORE(w[1], q_row + 16, 0);
            DEQUANT_STORE(w[2], q_row + 32, 0);
            DEQUANT_STORE(w[3], q_row + 48, 0);
        }
        QLOAD(nq1, 1);
        ISSUE_A(0, 0);
        ISSUE_A(BK, 1);
        asm volatile("cp.async.wait_group 1;\n");
        __syncthreads();

        #pragma unroll 3
        for (int i = 0; i < K_TILES; i++) {
            const int cur = i % 3;
            const int nxt = (i + 1) % 3;
            const int nn  = (i + 2) % 3;
            const bool hasn1 = (i + 1 < K_TILES);
            const bool hasn2 = (i + 2 < K_TILES);

            int nq2[4];
            if (hasn2) {
                QLOAD(nq2, i + 2);           // longest-latency loads issue first
                ISSUE_A((i + 2) * BK, nn);
            }
            if (hasn1 && (((i + 1) & 1) == 0)) LOAD_SCALES((i + 1) >> 1);

            MMA_KSTEP(0, cur);
            MMA_KSTEP(1, cur);

            if (hasn1) {
                DEQUANT_STORE(nq1[0], q_row,      nxt);
                DEQUANT_STORE(nq1[1], q_row + 16, nxt);
            }

            MMA_KSTEP(2, cur);

            if (hasn1) {
                DEQUANT_STORE(nq1[2], q_row + 32, nxt);
                DEQUANT_STORE(nq1[3], q_row + 48, nxt);
            }

            MMA_KSTEP(3, cur);

            if (hasn2)      asm volatile("cp.async.wait_group 1;\n");
            else if (hasn1) asm volatile("cp.async.wait_group 0;\n");
            __syncthreads();

            nq1[0] = nq2[0]; nq1[1] = nq2[1]; nq1[2] = nq2[2]; nq1[3] = nq2[3];
        }

        // ---- epilogue: round to f16 grid, streaming f32 stores ----
        const int r  = lane >> 2;
        const int cp = (lane & 3) * 2;
        #pragma unroll
        for (int mf = 0; mf < 4; mf++) {
            const int row_base = m0 + warp_m * 64 + mf * 16;
            #pragma unroll
            for (int nf = 0; nf < 4; nf++) {
                const int col = n0 + warp_n * 32 + nf * 8 + cp;
                float2 lo, hi;
                lo.x = __half2float(__float2half_rn(acc[mf][nf][0]));
                lo.y = __half2float(__float2half_rn(acc[mf][nf][1]));
                hi.x = __half2float(__float2half_rn(acc[mf][nf][2]));
                hi.y = __half2float(__float2half_rn(acc[mf][nf][3]));
                stg_cs_f2(C + (size_t)(row_base + r)     * N_DIM + col, lo);
                stg_cs_f2(C + (size_t)(row_base + r + 8) * N_DIM + col, hi);
            }
        }
    }
}

extern "C" void kernel_launch(void* const* d_in, const int* in_sizes, int n_in,
                              void* d_out, int out_size)
{
    const float* A      = (const float*)d_in[0];
    const int*   qw     = (const int*)d_in[1];
    const float* scales = (const float*)d_in[2];
    float*       C      = (float*)d_out;

    const size_t total = (size_t)M_TOTAL * K_DIM;
    convert_A_kernel<<<(unsigned)(total / 2048), 256>>>(A);

    cudaFuncSetAttribute(awq_gemm_kernel,
                         cudaFuncAttributeMaxDynamicSharedMemorySize, SMEM_TOTAL);
    awq_gemm_kernel<<<GRID, 256, SMEM_TOTAL>>>(qw, scales, C);
}